// round 2
// baseline (speedup 1.0000x reference)
#include <cuda_runtime.h>
#include <math.h>

// Problem constants
#define CB 2
#define CT 2048
#define CC 1024
#define CH 16
#define CD 64
#define NTOK (CB*CT)          // 4096
#define CHALF 512

// ---------------- scratch (device globals; no allocation) ----------------
__device__ float g_H   [NTOK*CC];   // hidden buffer (imp hidden uses first 4096x512)
__device__ float g_XI  [NTOK*CC];
__device__ float g_RSN [NTOK*CC];
__device__ float g_Q   [NTOK*CC];
__device__ float g_K   [NTOK*CC];
__device__ float g_V   [NTOK*CC];
__device__ float g_AO  [NTOK*CC];
__device__ float g_PRJ [NTOK*CC];
__device__ float g_MEANR[CB*CC];
__device__ float g_TEMP [CB*CH];

// ---------------- helpers ----------------
__device__ __forceinline__ void blockReduce2(float& a, float& b) {
    __shared__ float sa[32], sb[32];
    int lane = threadIdx.x & 31, wid = threadIdx.x >> 5;
    #pragma unroll
    for (int o = 16; o; o >>= 1) {
        a += __shfl_xor_sync(0xffffffffu, a, o);
        b += __shfl_xor_sync(0xffffffffu, b, o);
    }
    if (lane == 0) { sa[wid] = a; sb[wid] = b; }
    __syncthreads();
    int nw = blockDim.x >> 5;
    a = (lane < nw) ? sa[lane] : 0.f;
    b = (lane < nw) ? sb[lane] : 0.f;
    #pragma unroll
    for (int o = 16; o; o >>= 1) {
        a += __shfl_xor_sync(0xffffffffu, a, o);
        b += __shfl_xor_sync(0xffffffffu, b, o);
    }
}

__device__ __forceinline__ float gelu_exact(float v) {
    return 0.5f * v * (1.f + erff(v * 0.70710678118654752f));
}

// ---------------- SGEMM: C = A[M,K] @ W[K,N] + bias ----------------
// 128x128 tile, BK=16, 256 threads, 8x8 per thread. M%128==0, N%128==0, K%16==0.
__global__ __launch_bounds__(256) void sgemm_bias(
    const float* __restrict__ A, const float* __restrict__ W,
    const float* __restrict__ bias, float* __restrict__ C,
    int M, int N, int K)
{
    __shared__ float As[16][128];
    __shared__ float Bs[16][128];
    const int tid  = threadIdx.x;
    const int bx   = blockIdx.x, by = blockIdx.y;
    const int trow = tid >> 4, tcol = tid & 15;
    const int aRow = tid >> 2;          // 0..63
    const int aCol = (tid & 3) << 2;    // 0,4,8,12
    const int bRow = tid >> 5;          // 0..7
    const int bCol = (tid & 31) << 2;   // 0..124

    float acc[8][8];
    #pragma unroll
    for (int i = 0; i < 8; i++)
        #pragma unroll
        for (int j = 0; j < 8; j++) acc[i][j] = 0.f;

    const float* Ab = A + (size_t)(by * 128) * K;
    const float* Wb = W + bx * 128;

    for (int k0 = 0; k0 < K; k0 += 16) {
        #pragma unroll
        for (int i = 0; i < 2; i++) {
            int r = aRow + i * 64;
            float4 v = *(const float4*)(Ab + (size_t)r * K + k0 + aCol);
            As[aCol + 0][r] = v.x; As[aCol + 1][r] = v.y;
            As[aCol + 2][r] = v.z; As[aCol + 3][r] = v.w;
        }
        #pragma unroll
        for (int i = 0; i < 2; i++) {
            int r = bRow + i * 8;
            *(float4*)&Bs[r][bCol] = *(const float4*)(Wb + (size_t)(k0 + r) * N + bCol);
        }
        __syncthreads();
        #pragma unroll
        for (int kk = 0; kk < 16; kk++) {
            float ra[8], rb[8];
            *(float4*)&ra[0] = *(float4*)&As[kk][trow * 8];
            *(float4*)&ra[4] = *(float4*)&As[kk][trow * 8 + 4];
            *(float4*)&rb[0] = *(float4*)&Bs[kk][tcol * 8];
            *(float4*)&rb[4] = *(float4*)&Bs[kk][tcol * 8 + 4];
            #pragma unroll
            for (int i = 0; i < 8; i++)
                #pragma unroll
                for (int j = 0; j < 8; j++)
                    acc[i][j] += ra[i] * rb[j];
        }
        __syncthreads();
    }
    #pragma unroll
    for (int i = 0; i < 8; i++) {
        int row = by * 128 + trow * 8 + i;
        #pragma unroll
        for (int j = 0; j < 8; j++) {
            int col = bx * 128 + tcol * 8 + j;
            C[(size_t)row * N + col] = acc[i][j] + bias[col];
        }
    }
}

// ---------------- per-row LayerNorm (+optional exact GELU), in place ----------------
template<int N, bool DO_GELU>
__global__ __launch_bounds__(256) void ln_rows(float* __restrict__ data,
                                               const float* __restrict__ g,
                                               const float* __restrict__ beta)
{
    constexpr int PT = N / 256;
    int row = blockIdx.x;
    float* p = data + (size_t)row * N;
    float v[PT];
    float s = 0.f, s2 = 0.f;
    #pragma unroll
    for (int i = 0; i < PT; i++) {
        int c = threadIdx.x + i * 256;
        v[i] = p[c];
        s += v[i]; s2 += v[i] * v[i];
    }
    blockReduce2(s, s2);
    float mean = s * (1.f / N);
    float var  = s2 * (1.f / N) - mean * mean;
    float rstd = rsqrtf(var + 1e-5f);
    #pragma unroll
    for (int i = 0; i < PT; i++) {
        int c = threadIdx.x + i * 256;
        float t = (v[i] - mean) * rstd * g[c] + beta[c];
        if (DO_GELU) t = gelu_exact(t);
        p[c] = t;
    }
}

// ---------------- importance: sigmoid(h @ w2 + b2), xi = x * imp ----------------
__global__ __launch_bounds__(256) void importance_gate(
    const float* __restrict__ h, const float* __restrict__ w2,
    const float* __restrict__ b2, const float* __restrict__ x,
    float* __restrict__ xi)
{
    int row = blockIdx.x;
    const float* hp = h + (size_t)row * CHALF;
    float s = hp[threadIdx.x] * w2[threadIdx.x]
            + hp[threadIdx.x + 256] * w2[threadIdx.x + 256];
    float dummy = 0.f;
    blockReduce2(s, dummy);
    float imp = 1.f / (1.f + expf(-(s + b2[0])));
    imp = fmaxf(imp, 1e-6f);
    const float* xp = x + (size_t)row * CC;
    float* xip = xi + (size_t)row * CC;
    #pragma unroll
    for (int i = 0; i < 4; i++) {
        int c = threadIdx.x + i * 256;
        xip[c] = xp[c] * imp;
    }
}

// ---------------- mean over T per batch ----------------
__global__ __launch_bounds__(256) void mean_rows(const float* __restrict__ rsn,
                                                 float* __restrict__ meanr)
{
    int c = blockIdx.x * 256 + threadIdx.x;   // 0..1023
    int b = blockIdx.y;
    const float* p = rsn + (size_t)b * CT * CC + c;
    float s = 0.f;
    #pragma unroll 8
    for (int t = 0; t < CT; t++) s += p[(size_t)t * CC];
    meanr[b * CC + c] = s * (1.f / CT);
}

// ---------------- temperature net: softplus(GELU(LN(mean@w1+b1))@w2+b2)+0.5 ----------------
__global__ __launch_bounds__(512) void temp_net(
    const float* __restrict__ meanr,
    const float* __restrict__ w1, const float* __restrict__ b1,
    const float* __restrict__ g,  const float* __restrict__ beta,
    const float* __restrict__ w2, const float* __restrict__ b2,
    float* __restrict__ temp)
{
    int b = blockIdx.x, tid = threadIdx.x;
    __shared__ float mr[CC];
    __shared__ float hh[CHALF];
    mr[tid]       = meanr[b * CC + tid];
    mr[tid + 512] = meanr[b * CC + tid + 512];
    __syncthreads();

    float acc = b1[tid];
    #pragma unroll 4
    for (int k = 0; k < CC; k++) acc += mr[k] * w1[k * CHALF + tid];

    float s = acc, s2 = acc * acc;
    blockReduce2(s, s2);
    float mean = s * (1.f / CHALF);
    float var  = s2 * (1.f / CHALF) - mean * mean;
    float v = (acc - mean) * rsqrtf(var + 1e-5f) * g[tid] + beta[tid];
    hh[tid] = gelu_exact(v);
    __syncthreads();

    int w = tid >> 5, lane = tid & 31;   // 16 warps -> 16 heads
    float t = 0.f;
    for (int k = lane; k < CHALF; k += 32) t += hh[k] * w2[k * CH + w];
    #pragma unroll
    for (int o = 16; o; o >>= 1) t += __shfl_xor_sync(0xffffffffu, t, o);
    if (lane == 0) {
        t += b2[w];
        float sp = (t > 20.f) ? t : log1pf(expf(t));
        temp[b * CH + w] = sp + 0.5f;
    }
}

// ---------------- flash attention, fp32, Br=Bc=64, D=64 ----------------
// grid (T/64, H, B), 256 threads: rg=tid/16 -> 4 rows; cg=tid%16 -> 4 cols
// smem rows padded to 65 floats (stride 65 == 1 mod 32 banks -> conflict-free
// column reads). All smem stores are SCALAR (260 B row stride is not 16 B
// aligned; float4 STS would trap with misaligned address).
#define FLASH_SMEM (4 * 64 * 65 * 4)
__global__ __launch_bounds__(256) void flash_attn(
    const float* __restrict__ Q, const float* __restrict__ K,
    const float* __restrict__ V, const int* __restrict__ mask,
    const float* __restrict__ temp, float* __restrict__ O)
{
    extern __shared__ float sm[];
    float (*Qs)[65] = (float(*)[65])(sm);
    float (*Ks)[65] = (float(*)[65])(sm + 64 * 65);
    float (*Vs)[65] = (float(*)[65])(sm + 2 * 64 * 65);
    float (*Ps)[65] = (float(*)[65])(sm + 3 * 64 * 65);

    const int qt = blockIdx.x, h = blockIdx.y, b = blockIdx.z;
    const int tid = threadIdx.x;
    const int rg = tid >> 4, cg = tid & 15;
    const int r0 = rg * 4, c0 = cg * 4;
    const int base_q = b * CT + qt * 64;

    // load Q tile [64x64]: aligned float4 gmem load, scalar smem stores
    #pragma unroll
    for (int i = 0; i < 4; i++) {
        int fi = tid + i * 256;
        int r = fi >> 4, c4 = (fi & 15) << 2;
        float4 v = *(const float4*)(Q + (size_t)(base_q + r) * CC + h * 64 + c4);
        Qs[r][c4 + 0] = v.x; Qs[r][c4 + 1] = v.y;
        Qs[r][c4 + 2] = v.z; Qs[r][c4 + 3] = v.w;
    }

    const float sc = 0.125f * temp[b * CH + h];  // 1/sqrt(64) * temperature
    float m_i[4], l_i[4], Oa[4][4];
    #pragma unroll
    for (int i = 0; i < 4; i++) {
        m_i[i] = -1e30f; l_i[i] = 0.f;
        #pragma unroll
        for (int j = 0; j < 4; j++) Oa[i][j] = 0.f;
    }

    for (int kt = 0; kt < CT / 64; kt++) {
        __syncthreads();   // previous PV reads of Ks/Vs/Ps done
        const int base_k = b * CT + kt * 64;
        #pragma unroll
        for (int i = 0; i < 4; i++) {
            int fi = tid + i * 256;
            int r = fi >> 4, c4 = (fi & 15) << 2;
            float4 kv = *(const float4*)(K + (size_t)(base_k + r) * CC + h * 64 + c4);
            Ks[r][c4 + 0] = kv.x; Ks[r][c4 + 1] = kv.y;
            Ks[r][c4 + 2] = kv.z; Ks[r][c4 + 3] = kv.w;
            float4 vv = *(const float4*)(V + (size_t)(base_k + r) * CC + h * 64 + c4);
            Vs[r][c4 + 0] = vv.x; Vs[r][c4 + 1] = vv.y;
            Vs[r][c4 + 2] = vv.z; Vs[r][c4 + 3] = vv.w;
        }
        __syncthreads();

        // S = (Q K^T) * scale * temp
        float s[4][4];
        #pragma unroll
        for (int i = 0; i < 4; i++)
            #pragma unroll
            for (int j = 0; j < 4; j++) s[i][j] = 0.f;
        #pragma unroll 16
        for (int d = 0; d < 64; d++) {
            float qa[4], kb[4];
            #pragma unroll
            for (int i = 0; i < 4; i++) qa[i] = Qs[r0 + i][d];
            #pragma unroll
            for (int j = 0; j < 4; j++) kb[j] = Ks[c0 + j][d];
            #pragma unroll
            for (int i = 0; i < 4; i++)
                #pragma unroll
                for (int j = 0; j < 4; j++)
                    s[i][j] += qa[i] * kb[j];
        }

        // mask + online softmax (per owned row)
        #pragma unroll
        for (int i = 0; i < 4; i++) {
            int qrow = qt * 64 + r0 + i;
            int mbase = b * CT * CT + qrow * CT + kt * 64 + c0;
            float rm = -1e30f;
            #pragma unroll
            for (int j = 0; j < 4; j++) {
                float sv = s[i][j] * sc;
                if (mask[mbase + j] == 0) sv = -1e30f;
                s[i][j] = sv;
                rm = fmaxf(rm, sv);
            }
            #pragma unroll
            for (int o = 1; o < 16; o <<= 1)
                rm = fmaxf(rm, __shfl_xor_sync(0xffffffffu, rm, o));
            float mnew = fmaxf(m_i[i], rm);
            float corr = __expf(m_i[i] - mnew);
            float rs = 0.f;
            #pragma unroll
            for (int j = 0; j < 4; j++) {
                float pv = __expf(s[i][j] - mnew);
                s[i][j] = pv;
                rs += pv;
            }
            #pragma unroll
            for (int o = 1; o < 16; o <<= 1)
                rs += __shfl_xor_sync(0xffffffffu, rs, o);
            l_i[i] = l_i[i] * corr + rs;
            m_i[i] = mnew;
            #pragma unroll
            for (int j = 0; j < 4; j++) Oa[i][j] *= corr;
            #pragma unroll
            for (int j = 0; j < 4; j++) Ps[r0 + i][c0 + j] = s[i][j];
        }
        __syncthreads();

        // O += P @ V
        #pragma unroll 16
        for (int k = 0; k < 64; k++) {
            float pv[4], vv[4];
            #pragma unroll
            for (int i = 0; i < 4; i++) pv[i] = Ps[r0 + i][k];
            #pragma unroll
            for (int j = 0; j < 4; j++) vv[j] = Vs[k][c0 + j];
            #pragma unroll
            for (int i = 0; i < 4; i++)
                #pragma unroll
                for (int j = 0; j < 4; j++)
                    Oa[i][j] += pv[i] * vv[j];
        }
    }

    #pragma unroll
    for (int i = 0; i < 4; i++) {
        float inv = 1.f / l_i[i];
        #pragma unroll
        for (int j = 0; j < 4; j++)
            O[(size_t)(base_q + r0 + i) * CC + h * 64 + c0 + j] = Oa[i][j] * inv;
    }
}

// ---------------- residual + final LN -> out ----------------
__global__ __launch_bounds__(256) void residual_ln(
    const float* __restrict__ x, const float* __restrict__ y,
    const float* __restrict__ g, const float* __restrict__ beta,
    float* __restrict__ out)
{
    int row = blockIdx.x;
    const float* xp = x + (size_t)row * CC;
    const float* yp = y + (size_t)row * CC;
    float v[4];
    float s = 0.f, s2 = 0.f;
    #pragma unroll
    for (int i = 0; i < 4; i++) {
        int c = threadIdx.x + i * 256;
        float t = xp[c] + yp[c];
        v[i] = t; s += t; s2 += t * t;
    }
    blockReduce2(s, s2);
    float mean = s * (1.f / CC);
    float var  = s2 * (1.f / CC) - mean * mean;
    float rstd = rsqrtf(var + 1e-5f);
    #pragma unroll
    for (int i = 0; i < 4; i++) {
        int c = threadIdx.x + i * 256;
        out[(size_t)row * CC + c] = (v[i] - mean) * rstd * g[c] + beta[c];
    }
}

// ---------------- launcher ----------------
extern "C" void kernel_launch(void* const* d_in, const int* in_sizes, int n_in,
                              void* d_out, int out_size)
{
    const float* x        = (const float*)d_in[0];
    const int*   mask     = (const int*)  d_in[1];
    const float* imp_w1   = (const float*)d_in[2];
    const float* imp_b1   = (const float*)d_in[3];
    const float* imp_g    = (const float*)d_in[4];
    const float* imp_beta = (const float*)d_in[5];
    const float* imp_w2   = (const float*)d_in[6];
    const float* imp_b2   = (const float*)d_in[7];
    const float* rsn_w1   = (const float*)d_in[8];
    const float* rsn_b1   = (const float*)d_in[9];
    const float* rsn_g    = (const float*)d_in[10];
    const float* rsn_beta = (const float*)d_in[11];
    const float* rsn_w2   = (const float*)d_in[12];
    const float* rsn_b2   = (const float*)d_in[13];
    const float* q_w      = (const float*)d_in[14];
    const float* q_b      = (const float*)d_in[15];
    const float* k_w      = (const float*)d_in[16];
    const float* k_b      = (const float*)d_in[17];
    const float* v_w      = (const float*)d_in[18];
    const float* v_b      = (const float*)d_in[19];
    const float* o_w      = (const float*)d_in[20];
    const float* o_b      = (const float*)d_in[21];
    const float* tmp_w1   = (const float*)d_in[22];
    const float* tmp_b1   = (const float*)d_in[23];
    const float* tmp_g    = (const float*)d_in[24];
    const float* tmp_beta = (const float*)d_in[25];
    const float* tmp_w2   = (const float*)d_in[26];
    const float* tmp_b2   = (const float*)d_in[27];
    const float* norm_g   = (const float*)d_in[28];
    const float* norm_b   = (const float*)d_in[29];
    float* out = (float*)d_out;

    float *H, *XI, *RSN, *Qb, *Kb, *Vb, *AO, *PRJ, *MEANR, *TEMP;
    cudaGetSymbolAddress((void**)&H,     g_H);
    cudaGetSymbolAddress((void**)&XI,    g_XI);
    cudaGetSymbolAddress((void**)&RSN,   g_RSN);
    cudaGetSymbolAddress((void**)&Qb,    g_Q);
    cudaGetSymbolAddress((void**)&Kb,    g_K);
    cudaGetSymbolAddress((void**)&Vb,    g_V);
    cudaGetSymbolAddress((void**)&AO,    g_AO);
    cudaGetSymbolAddress((void**)&PRJ,   g_PRJ);
    cudaGetSymbolAddress((void**)&MEANR, g_MEANR);
    cudaGetSymbolAddress((void**)&TEMP,  g_TEMP);

    cudaFuncSetAttribute(flash_attn, cudaFuncAttributeMaxDynamicSharedMemorySize,
                         FLASH_SMEM);

    dim3 g512(CHALF / 128, NTOK / 128);   // (4, 32)
    dim3 g1024(CC / 128, NTOK / 128);     // (8, 32)

    // importance net
    sgemm_bias<<<g512, 256>>>(x, imp_w1, imp_b1, H, NTOK, CHALF, CC);
    ln_rows<CHALF, true><<<NTOK, 256>>>(H, imp_g, imp_beta);
    importance_gate<<<NTOK, 256>>>(H, imp_w2, imp_b2, x, XI);

    // reasoning net
    sgemm_bias<<<g1024, 256>>>(XI, rsn_w1, rsn_b1, H, NTOK, CC, CC);
    ln_rows<CC, true><<<NTOK, 256>>>(H, rsn_g, rsn_beta);
    sgemm_bias<<<g1024, 256>>>(H, rsn_w2, rsn_b2, RSN, NTOK, CC, CC);

    // projections
    sgemm_bias<<<g1024, 256>>>(RSN, q_w, q_b, Qb, NTOK, CC, CC);
    sgemm_bias<<<g1024, 256>>>(XI,  k_w, k_b, Kb, NTOK, CC, CC);
    sgemm_bias<<<g1024, 256>>>(x,   v_w, v_b, Vb, NTOK, CC, CC);

    // temperature
    mean_rows<<<dim3(CC / 256, CB), 256>>>(RSN, MEANR);
    temp_net<<<CB, 512>>>(MEANR, tmp_w1, tmp_b1, tmp_g, tmp_beta,
                          tmp_w2, tmp_b2, TEMP);

    // attention
    flash_attn<<<dim3(CT / 64, CH, CB), 256, FLASH_SMEM>>>(Qb, Kb, Vb, mask,
                                                           TEMP, AO);

    // output projection + residual LN
    sgemm_bias<<<g1024, 256>>>(AO, o_w, o_b, PRJ, NTOK, CC, CC);
    residual_ln<<<NTOK, 256>>>(x, PRJ, norm_g, norm_b, out);
}

// round 5
// speedup vs baseline: 1.4540x; 1.4540x over previous
#include <cuda_runtime.h>
#include <cuda_bf16.h>
#include <math.h>
#include <stdint.h>

// Problem constants
#define CB 2
#define CT 2048
#define CC 1024
#define CH 16
#define CD 64
#define NTOK (CB*CT)          // 4096
#define CHALF 512

// ---------------- scratch (device globals; no allocation) ----------------
__device__ float g_H   [NTOK*CC];
__device__ float g_XI  [NTOK*CC];
__device__ float g_RSN [NTOK*CC];
__device__ float g_Q   [NTOK*CC];
__device__ float g_K   [NTOK*CC];
__device__ float g_V   [NTOK*CC];
__device__ float g_AO  [NTOK*CC];
__device__ float g_PRJ [NTOK*CC];
__device__ float g_MEANR[CB*CC];
__device__ float g_TEMP [CB*CH];

// bf16 split weights, transposed to [N,K] K-major
__device__ __nv_bfloat16 g_wi1h[CHALF*CC], g_wi1l[CHALF*CC];
__device__ __nv_bfloat16 g_wr1h[CC*CC],   g_wr1l[CC*CC];
__device__ __nv_bfloat16 g_wr2h[CC*CC],   g_wr2l[CC*CC];
__device__ __nv_bfloat16 g_wqh [CC*CC],   g_wql [CC*CC];
__device__ __nv_bfloat16 g_wkh [CC*CC],   g_wkl [CC*CC];
__device__ __nv_bfloat16 g_wvh [CC*CC],   g_wvl [CC*CC];
__device__ __nv_bfloat16 g_woh [CC*CC],   g_wol [CC*CC];
// bf16 split activations
__device__ __nv_bfloat16 g_Xh [NTOK*CC], g_Xl [NTOK*CC];
__device__ __nv_bfloat16 g_XIh[NTOK*CC], g_XIl[NTOK*CC];
__device__ __nv_bfloat16 g_Hh [NTOK*CC], g_Hl [NTOK*CC];
__device__ __nv_bfloat16 g_Rh [NTOK*CC], g_Rl [NTOK*CC];
__device__ __nv_bfloat16 g_Ahb[NTOK*CC], g_Alb[NTOK*CC];

// ---------------- helpers ----------------
__device__ __forceinline__ void blockReduce2(float& a, float& b) {
    __shared__ float sa[32], sb[32];
    int lane = threadIdx.x & 31, wid = threadIdx.x >> 5;
    #pragma unroll
    for (int o = 16; o; o >>= 1) {
        a += __shfl_xor_sync(0xffffffffu, a, o);
        b += __shfl_xor_sync(0xffffffffu, b, o);
    }
    if (lane == 0) { sa[wid] = a; sb[wid] = b; }
    __syncthreads();
    int nw = blockDim.x >> 5;
    a = (lane < nw) ? sa[lane] : 0.f;
    b = (lane < nw) ? sb[lane] : 0.f;
    #pragma unroll
    for (int o = 16; o; o >>= 1) {
        a += __shfl_xor_sync(0xffffffffu, a, o);
        b += __shfl_xor_sync(0xffffffffu, b, o);
    }
}

__device__ __forceinline__ float gelu_exact(float v) {
    return 0.5f * v * (1.f + erff(v * 0.70710678118654752f));
}

__device__ __forceinline__ uint32_t smem_u32(const void* p) {
    uint32_t a;
    asm("{ .reg .u64 t; cvta.to.shared.u64 t, %1; cvt.u32.u64 %0, t; }"
        : "=r"(a) : "l"(p));
    return a;
}

__device__ __forceinline__ void ldsm4(uint32_t& r0, uint32_t& r1,
                                      uint32_t& r2, uint32_t& r3, uint32_t addr) {
    asm volatile("ldmatrix.sync.aligned.m8n8.x4.shared.b16 {%0,%1,%2,%3}, [%4];"
                 : "=r"(r0), "=r"(r1), "=r"(r2), "=r"(r3) : "r"(addr));
}

__device__ __forceinline__ void mma16816(float* c, const uint32_t* a,
                                         uint32_t b0, uint32_t b1) {
    asm volatile(
        "mma.sync.aligned.m16n8k16.row.col.f32.bf16.bf16.f32 "
        "{%0,%1,%2,%3}, {%4,%5,%6,%7}, {%8,%9}, {%0,%1,%2,%3};"
        : "+f"(c[0]), "+f"(c[1]), "+f"(c[2]), "+f"(c[3])
        : "r"(a[0]), "r"(a[1]), "r"(a[2]), "r"(a[3]), "r"(b0), "r"(b1));
}

// ---------------- weight transpose + split: W[K,N] fp32 -> hiT/loT [N,K] bf16 ----------------
__global__ __launch_bounds__(256) void wsplit(
    const float* __restrict__ W,
    __nv_bfloat16* __restrict__ hiT, __nv_bfloat16* __restrict__ loT,
    int K, int N)
{
    __shared__ float t[32][33];
    int tx = threadIdx.x & 31, ty = threadIdx.x >> 5;   // 32x8
    int n0 = blockIdx.x * 32, k0 = blockIdx.y * 32;
    #pragma unroll
    for (int i = 0; i < 4; i++)
        t[ty + i * 8][tx] = W[(size_t)(k0 + ty + i * 8) * N + n0 + tx];
    __syncthreads();
    #pragma unroll
    for (int i = 0; i < 4; i++) {
        float v = t[tx][ty + i * 8];
        __nv_bfloat16 h = __float2bfloat16_rn(v);
        __nv_bfloat16 l = __float2bfloat16_rn(v - __bfloat162float(h));
        size_t o = (size_t)(n0 + ty + i * 8) * K + k0 + tx;
        hiT[o] = h; loT[o] = l;
    }
}

// ---------------- activation split: fp32 -> bf16 hi + lo ----------------
__global__ __launch_bounds__(256) void asplit(
    const float4* __restrict__ A,
    uint2* __restrict__ hi, uint2* __restrict__ lo)
{
    int i = blockIdx.x * 256 + threadIdx.x;   // each handles 4 floats
    float4 v = A[i];
    union { __nv_bfloat16 b[4]; uint2 u; } ph, pl;
    #pragma unroll
    for (int j = 0; j < 4; j++) {
        float f = (&v.x)[j];
        __nv_bfloat16 h = __float2bfloat16_rn(f);
        ph.b[j] = h;
        pl.b[j] = __float2bfloat16_rn(f - __bfloat162float(h));
    }
    hi[i] = ph.u;
    lo[i] = pl.u;
}

// ---------------- HMMA GEMM: C[M,N] = A[M,1024] @ W[1024,N] + bias ----------------
// A split bf16 [M,1024] row-major; W split bf16 [N,1024] K-major (transposed).
// 128x128 CTA tile, BK=32, 8 warps (4 along M x 2 along N), warp tile 32x64.
// Split precision: hi*hi + hi*lo + lo*hi accumulated in fp32.
#define PAD 40   // bf16 per smem row (80 B): 8 ldmatrix rows hit distinct 16B slots mod 128B

__global__ __launch_bounds__(256) void gemm_mma(
    const __nv_bfloat16* __restrict__ Ah, const __nv_bfloat16* __restrict__ Al,
    const __nv_bfloat16* __restrict__ Bh, const __nv_bfloat16* __restrict__ Bl,
    const float* __restrict__ bias, float* __restrict__ C, int N)
{
    __shared__ __nv_bfloat16 sA[2][128][PAD];   // [hi/lo][m][k]
    __shared__ __nv_bfloat16 sB[2][128][PAD];   // [hi/lo][n][k]

    const int tid  = threadIdx.x;
    const int wid  = tid >> 5, lane = tid & 31;
    const int m0   = blockIdx.y * 128, n0 = blockIdx.x * 128;
    const int wm   = (wid & 3) * 32;    // warp m offset
    const int wn   = (wid >> 2) * 64;   // warp n offset

    // loader mapping: tile row lr, 16-col segment lc
    const int lr = tid >> 1;
    const int lc = (tid & 1) * 16;

    const __nv_bfloat16* gA[2] = { Ah + (size_t)(m0 + lr) * 1024 + lc,
                                   Al + (size_t)(m0 + lr) * 1024 + lc };
    const __nv_bfloat16* gB[2] = { Bh + (size_t)(n0 + lr) * 1024 + lc,
                                   Bl + (size_t)(n0 + lr) * 1024 + lc };

    float acc[2][8][4];
    #pragma unroll
    for (int i = 0; i < 2; i++)
        #pragma unroll
        for (int j = 0; j < 8; j++)
            #pragma unroll
            for (int k = 0; k < 4; k++) acc[i][j][k] = 0.f;

    // per-lane ldmatrix base offsets (bytes)
    // A frag (m16k16): addr = &sA[s][wm + mt*16 + (lane&15)][ks*16 + (lane>>4)*8]
    const int aRow = wm + (lane & 15);
    const int aCol = (lane >> 4) * 8;
    // B frag pair (2 n-tiles x k16): n = wn + jp*16 + (lane>>4)*8 + (lane&7),
    //                                k = ks*16 + ((lane>>3)&1)*8
    const int bRow = wn + (lane >> 4) * 8 + (lane & 7);
    const int bCol = ((lane >> 3) & 1) * 8;

    uint32_t baseA[2], baseB[2];
    baseA[0] = smem_u32(&sA[0][0][0]); baseA[1] = smem_u32(&sA[1][0][0]);
    baseB[0] = smem_u32(&sB[0][0][0]); baseB[1] = smem_u32(&sB[1][0][0]);

    uint4 pa[2][2], pb[2][2];
    // prefetch chunk 0
    #pragma unroll
    for (int s = 0; s < 2; s++) {
        pa[s][0] = *(const uint4*)(gA[s]);     pa[s][1] = *(const uint4*)(gA[s] + 8);
        pb[s][0] = *(const uint4*)(gB[s]);     pb[s][1] = *(const uint4*)(gB[s] + 8);
    }

    for (int c = 0; c < 32; c++) {
        // store prefetched chunk to smem
        #pragma unroll
        for (int s = 0; s < 2; s++) {
            *(uint4*)&sA[s][lr][lc]     = pa[s][0];
            *(uint4*)&sA[s][lr][lc + 8] = pa[s][1];
            *(uint4*)&sB[s][lr][lc]     = pb[s][0];
            *(uint4*)&sB[s][lr][lc + 8] = pb[s][1];
        }
        __syncthreads();

        // prefetch next chunk while computing this one
        if (c + 1 < 32) {
            const int off = (c + 1) * 32;
            #pragma unroll
            for (int s = 0; s < 2; s++) {
                pa[s][0] = *(const uint4*)(gA[s] + off);
                pa[s][1] = *(const uint4*)(gA[s] + off + 8);
                pb[s][0] = *(const uint4*)(gB[s] + off);
                pb[s][1] = *(const uint4*)(gB[s] + off + 8);
            }
        }

        #pragma unroll
        for (int ks = 0; ks < 2; ks++) {
            uint32_t afr[2][2][4];   // [split][mtile][4]
            #pragma unroll
            for (int s = 0; s < 2; s++)
                #pragma unroll
                for (int mt = 0; mt < 2; mt++) {
                    uint32_t addr = baseA[s] +
                        (uint32_t)(((aRow + mt * 16) * PAD + ks * 16 + aCol) * 2);
                    ldsm4(afr[s][mt][0], afr[s][mt][1], afr[s][mt][2], afr[s][mt][3], addr);
                }
            uint32_t bfr[2][4][4];   // [split][jpair][4]
            #pragma unroll
            for (int s = 0; s < 2; s++)
                #pragma unroll
                for (int jp = 0; jp < 4; jp++) {
                    uint32_t addr = baseB[s] +
                        (uint32_t)(((bRow + jp * 16) * PAD + ks * 16 + bCol) * 2);
                    ldsm4(bfr[s][jp][0], bfr[s][jp][1], bfr[s][jp][2], bfr[s][jp][3], addr);
                }
            #pragma unroll
            for (int mt = 0; mt < 2; mt++)
                #pragma unroll
                for (int j = 0; j < 8; j++) {
                    const int jp = j >> 1, hp = (j & 1) * 2;
                    uint32_t bh0 = bfr[0][jp][hp], bh1 = bfr[0][jp][hp + 1];
                    uint32_t bl0 = bfr[1][jp][hp], bl1 = bfr[1][jp][hp + 1];
                    mma16816(acc[mt][j], afr[0][mt], bh0, bh1);   // hi*hi
                    mma16816(acc[mt][j], afr[0][mt], bl0, bl1);   // hi*lo
                    mma16816(acc[mt][j], afr[1][mt], bh0, bh1);   // lo*hi
                }
        }
        __syncthreads();
    }

    // epilogue
    #pragma unroll
    for (int mt = 0; mt < 2; mt++) {
        #pragma unroll
        for (int j = 0; j < 8; j++) {
            int row = m0 + wm + mt * 16 + (lane >> 2);
            int col = n0 + wn + j * 8 + (lane & 3) * 2;
            float b0 = bias[col], b1 = bias[col + 1];
            float2 o0 = { acc[mt][j][0] + b0, acc[mt][j][1] + b1 };
            float2 o1 = { acc[mt][j][2] + b0, acc[mt][j][3] + b1 };
            *(float2*)(C + (size_t)row * N + col)       = o0;
            *(float2*)(C + (size_t)(row + 8) * N + col) = o1;
        }
    }
}

// ---------------- per-row LayerNorm (+optional exact GELU), in place ----------------
template<int N, bool DO_GELU>
__global__ __launch_bounds__(256) void ln_rows(float* __restrict__ data,
                                               const float* __restrict__ g,
                                               const float* __restrict__ beta)
{
    constexpr int PT = N / 256;
    int row = blockIdx.x;
    float* p = data + (size_t)row * N;
    float v[PT];
    float s = 0.f, s2 = 0.f;
    #pragma unroll
    for (int i = 0; i < PT; i++) {
        int c = threadIdx.x + i * 256;
        v[i] = p[c];
        s += v[i]; s2 += v[i] * v[i];
    }
    blockReduce2(s, s2);
    float mean = s * (1.f / N);
    float var  = s2 * (1.f / N) - mean * mean;
    float rstd = rsqrtf(var + 1e-5f);
    #pragma unroll
    for (int i = 0; i < PT; i++) {
        int c = threadIdx.x + i * 256;
        float t = (v[i] - mean) * rstd * g[c] + beta[c];
        if (DO_GELU) t = gelu_exact(t);
        p[c] = t;
    }
}

// ---------------- importance: sigmoid(h @ w2 + b2), xi = x * imp ----------------
__global__ __launch_bounds__(256) void importance_gate(
    const float* __restrict__ h, const float* __restrict__ w2,
    const float* __restrict__ b2, const float* __restrict__ x,
    float* __restrict__ xi)
{
    int row = blockIdx.x;
    const float* hp = h + (size_t)row * CHALF;
    float s = hp[threadIdx.x] * w2[threadIdx.x]
            + hp[threadIdx.x + 256] * w2[threadIdx.x + 256];
    float dummy = 0.f;
    blockReduce2(s, dummy);
    float imp = 1.f / (1.f + expf(-(s + b2[0])));
    imp = fmaxf(imp, 1e-6f);
    const float* xp = x + (size_t)row * CC;
    float* xip = xi + (size_t)row * CC;
    #pragma unroll
    for (int i = 0; i < 4; i++) {
        int c = threadIdx.x + i * 256;
        xip[c] = xp[c] * imp;
    }
}

// ---------------- mean over T per batch ----------------
__global__ __launch_bounds__(256) void mean_rows(const float* __restrict__ rsn,
                                                 float* __restrict__ meanr)
{
    int c = blockIdx.x * 256 + threadIdx.x;
    int b = blockIdx.y;
    const float* p = rsn + (size_t)b * CT * CC + c;
    float s = 0.f;
    #pragma unroll 8
    for (int t = 0; t < CT; t++) s += p[(size_t)t * CC];
    meanr[b * CC + c] = s * (1.f / CT);
}

// ---------------- temperature net ----------------
__global__ __launch_bounds__(512) void temp_net(
    const float* __restrict__ meanr,
    const float* __restrict__ w1, const float* __restrict__ b1,
    const float* __restrict__ g,  const float* __restrict__ beta,
    const float* __restrict__ w2, const float* __restrict__ b2,
    float* __restrict__ temp)
{
    int b = blockIdx.x, tid = threadIdx.x;
    __shared__ float mr[CC];
    __shared__ float hh[CHALF];
    mr[tid]       = meanr[b * CC + tid];
    mr[tid + 512] = meanr[b * CC + tid + 512];
    __syncthreads();

    float acc = b1[tid];
    #pragma unroll 4
    for (int k = 0; k < CC; k++) acc += mr[k] * w1[k * CHALF + tid];

    float s = acc, s2 = acc * acc;
    blockReduce2(s, s2);
    float mean = s * (1.f / CHALF);
    float var  = s2 * (1.f / CHALF) - mean * mean;
    float v = (acc - mean) * rsqrtf(var + 1e-5f) * g[tid] + beta[tid];
    hh[tid] = gelu_exact(v);
    __syncthreads();

    int w = tid >> 5, lane = tid & 31;
    float t = 0.f;
    for (int k = lane; k < CHALF; k += 32) t += hh[k] * w2[k * CH + w];
    #pragma unroll
    for (int o = 16; o; o >>= 1) t += __shfl_xor_sync(0xffffffffu, t, o);
    if (lane == 0) {
        t += b2[w];
        float sp = (t > 20.f) ? t : log1pf(expf(t));
        temp[b * CH + w] = sp + 0.5f;
    }
}

// ---------------- flash attention, fp32, Br=Bc=64, D=64 ----------------
#define FLASH_SMEM (4 * 64 * 65 * 4)
__global__ __launch_bounds__(256) void flash_attn(
    const float* __restrict__ Q, const float* __restrict__ K,
    const float* __restrict__ V, const int* __restrict__ mask,
    const float* __restrict__ temp, float* __restrict__ O)
{
    extern __shared__ float sm[];
    float (*Qs)[65] = (float(*)[65])(sm);
    float (*Ks)[65] = (float(*)[65])(sm + 64 * 65);
    float (*Vs)[65] = (float(*)[65])(sm + 2 * 64 * 65);
    float (*Ps)[65] = (float(*)[65])(sm + 3 * 64 * 65);

    const int qt = blockIdx.x, h = blockIdx.y, b = blockIdx.z;
    const int tid = threadIdx.x;
    const int rg = tid >> 4, cg = tid & 15;
    const int r0 = rg * 4, c0 = cg * 4;
    const int base_q = b * CT + qt * 64;

    #pragma unroll
    for (int i = 0; i < 4; i++) {
        int fi = tid + i * 256;
        int r = fi >> 4, c4 = (fi & 15) << 2;
        float4 v = *(const float4*)(Q + (size_t)(base_q + r) * CC + h * 64 + c4);
        Qs[r][c4 + 0] = v.x; Qs[r][c4 + 1] = v.y;
        Qs[r][c4 + 2] = v.z; Qs[r][c4 + 3] = v.w;
    }

    const float sc = 0.125f * temp[b * CH + h];
    float m_i[4], l_i[4], Oa[4][4];
    #pragma unroll
    for (int i = 0; i < 4; i++) {
        m_i[i] = -1e30f; l_i[i] = 0.f;
        #pragma unroll
        for (int j = 0; j < 4; j++) Oa[i][j] = 0.f;
    }

    for (int kt = 0; kt < CT / 64; kt++) {
        __syncthreads();
        const int base_k = b * CT + kt * 64;
        #pragma unroll
        for (int i = 0; i < 4; i++) {
            int fi = tid + i * 256;
            int r = fi >> 4, c4 = (fi & 15) << 2;
            float4 kv = *(const float4*)(K + (size_t)(base_k + r) * CC + h * 64 + c4);
            Ks[r][c4 + 0] = kv.x; Ks[r][c4 + 1] = kv.y;
            Ks[r][c4 + 2] = kv.z; Ks[r][c4 + 3] = kv.w;
            float4 vv = *(const float4*)(V + (size_t)(base_k + r) * CC + h * 64 + c4);
            Vs[r][c4 + 0] = vv.x; Vs[r][c4 + 1] = vv.y;
            Vs[r][c4 + 2] = vv.z; Vs[r][c4 + 3] = vv.w;
        }
        __syncthreads();

        float s[4][4];
        #pragma unroll
        for (int i = 0; i < 4; i++)
            #pragma unroll
            for (int j = 0; j < 4; j++) s[i][j] = 0.f;
        #pragma unroll 16
        for (int d = 0; d < 64; d++) {
            float qa[4], kb[4];
            #pragma unroll
            for (int i = 0; i < 4; i++) qa[i] = Qs[r0 + i][d];
            #pragma unroll
            for (int j = 0; j < 4; j++) kb[j] = Ks[c0 + j][d];
            #pragma unroll
            for (int i = 0; i < 4; i++)
                #pragma unroll
                for (int j = 0; j < 4; j++)
                    s[i][j] += qa[i] * kb[j];
        }

        #pragma unroll
        for (int i = 0; i < 4; i++) {
            int qrow = qt * 64 + r0 + i;
            int mbase = b * CT * CT + qrow * CT + kt * 64 + c0;
            float rm = -1e30f;
            #pragma unroll
            for (int j = 0; j < 4; j++) {
                float sv = s[i][j] * sc;
                if (mask[mbase + j] == 0) sv = -1e30f;
                s[i][j] = sv;
                rm = fmaxf(rm, sv);
            }
            #pragma unroll
            for (int o = 1; o < 16; o <<= 1)
                rm = fmaxf(rm, __shfl_xor_sync(0xffffffffu, rm, o));
            float mnew = fmaxf(m_i[i], rm);
            float corr = __expf(m_i[i] - mnew);
            float rs = 0.f;
            #pragma unroll
            for (int j = 0; j < 4; j++) {
                float pv = __expf(s[i][j] - mnew);
                s[i][j] = pv;
                rs += pv;
            }
            #pragma unroll
            for (int o = 1; o < 16; o <<= 1)
                rs += __shfl_xor_sync(0xffffffffu, rs, o);
            l_i[i] = l_i[i] * corr + rs;
            m_i[i] = mnew;
            #pragma unroll
            for (int j = 0; j < 4; j++) Oa[i][j] *= corr;
            #pragma unroll
            for (int j = 0; j < 4; j++) Ps[r0 + i][c0 + j] = s[i][j];
        }
        __syncthreads();

        #pragma unroll 16
        for (int k = 0; k < 64; k++) {
            float pv[4], vv[4];
            #pragma unroll
            for (int i = 0; i < 4; i++) pv[i] = Ps[r0 + i][k];
            #pragma unroll
            for (int j = 0; j < 4; j++) vv[j] = Vs[k][c0 + j];
            #pragma unroll
            for (int i = 0; i < 4; i++)
                #pragma unroll
                for (int j = 0; j < 4; j++)
                    Oa[i][j] += pv[i] * vv[j];
        }
    }

    #pragma unroll
    for (int i = 0; i < 4; i++) {
        float inv = 1.f / l_i[i];
        #pragma unroll
        for (int j = 0; j < 4; j++)
            O[(size_t)(base_q + r0 + i) * CC + h * 64 + c0 + j] = Oa[i][j] * inv;
    }
}

// ---------------- residual + final LN -> out ----------------
__global__ __launch_bounds__(256) void residual_ln(
    const float* __restrict__ x, const float* __restrict__ y,
    const float* __restrict__ g, const float* __restrict__ beta,
    float* __restrict__ out)
{
    int row = blockIdx.x;
    const float* xp = x + (size_t)row * CC;
    const float* yp = y + (size_t)row * CC;
    float v[4];
    float s = 0.f, s2 = 0.f;
    #pragma unroll
    for (int i = 0; i < 4; i++) {
        int c = threadIdx.x + i * 256;
        float t = xp[c] + yp[c];
        v[i] = t; s += t; s2 += t * t;
    }
    blockReduce2(s, s2);
    float mean = s * (1.f / CC);
    float var  = s2 * (1.f / CC) - mean * mean;
    float rstd = rsqrtf(var + 1e-5f);
    #pragma unroll
    for (int i = 0; i < 4; i++) {
        int c = threadIdx.x + i * 256;
        out[(size_t)row * CC + c] = (v[i] - mean) * rstd * g[c] + beta[c];
    }
}

// ---------------- launcher ----------------
extern "C" void kernel_launch(void* const* d_in, const int* in_sizes, int n_in,
                              void* d_out, int out_size)
{
    const float* x        = (const float*)d_in[0];
    const int*   mask     = (const int*)  d_in[1];
    const float* imp_w1   = (const float*)d_in[2];
    const float* imp_b1   = (const float*)d_in[3];
    const float* imp_g    = (const float*)d_in[4];
    const float* imp_beta = (const float*)d_in[5];
    const float* imp_w2   = (const float*)d_in[6];
    const float* imp_b2   = (const float*)d_in[7];
    const float* rsn_w1   = (const float*)d_in[8];
    const float* rsn_b1   = (const float*)d_in[9];
    const float* rsn_g    = (const float*)d_in[10];
    const float* rsn_beta = (const float*)d_in[11];
    const float* rsn_w2   = (const float*)d_in[12];
    const float* rsn_b2   = (const float*)d_in[13];
    const float* q_w      = (const float*)d_in[14];
    const float* q_b      = (const float*)d_in[15];
    const float* k_w      = (const float*)d_in[16];
    const float* k_b      = (const float*)d_in[17];
    const float* v_w      = (const float*)d_in[18];
    const float* v_b      = (const float*)d_in[19];
    const float* o_w      = (const float*)d_in[20];
    const float* o_b      = (const float*)d_in[21];
    const float* tmp_w1   = (const float*)d_in[22];
    const float* tmp_b1   = (const float*)d_in[23];
    const float* tmp_g    = (const float*)d_in[24];
    const float* tmp_beta = (const float*)d_in[25];
    const float* tmp_w2   = (const float*)d_in[26];
    const float* tmp_b2   = (const float*)d_in[27];
    const float* norm_g   = (const float*)d_in[28];
    const float* norm_b   = (const float*)d_in[29];
    float* out = (float*)d_out;

    float *H, *XI, *RSN, *Qb, *Kb, *Vb, *AO, *PRJ, *MEANR, *TEMP;
    cudaGetSymbolAddress((void**)&H,     g_H);
    cudaGetSymbolAddress((void**)&XI,    g_XI);
    cudaGetSymbolAddress((void**)&RSN,   g_RSN);
    cudaGetSymbolAddress((void**)&Qb,    g_Q);
    cudaGetSymbolAddress((void**)&Kb,    g_K);
    cudaGetSymbolAddress((void**)&Vb,    g_V);
    cudaGetSymbolAddress((void**)&AO,    g_AO);
    cudaGetSymbolAddress((void**)&PRJ,   g_PRJ);
    cudaGetSymbolAddress((void**)&MEANR, g_MEANR);
    cudaGetSymbolAddress((void**)&TEMP,  g_TEMP);

    __nv_bfloat16 *wi1h,*wi1l,*wr1h,*wr1l,*wr2h,*wr2l,*wqh,*wql,*wkh,*wkl,*wvh,*wvl,*woh,*wol;
    __nv_bfloat16 *Xh,*Xl,*XIh,*XIl,*Hh,*Hl,*Rh,*Rl,*Ahb,*Alb;
    cudaGetSymbolAddress((void**)&wi1h, g_wi1h); cudaGetSymbolAddress((void**)&wi1l, g_wi1l);
    cudaGetSymbolAddress((void**)&wr1h, g_wr1h); cudaGetSymbolAddress((void**)&wr1l, g_wr1l);
    cudaGetSymbolAddress((void**)&wr2h, g_wr2h); cudaGetSymbolAddress((void**)&wr2l, g_wr2l);
    cudaGetSymbolAddress((void**)&wqh,  g_wqh);  cudaGetSymbolAddress((void**)&wql,  g_wql);
    cudaGetSymbolAddress((void**)&wkh,  g_wkh);  cudaGetSymbolAddress((void**)&wkl,  g_wkl);
    cudaGetSymbolAddress((void**)&wvh,  g_wvh);  cudaGetSymbolAddress((void**)&wvl,  g_wvl);
    cudaGetSymbolAddress((void**)&woh,  g_woh);  cudaGetSymbolAddress((void**)&wol,  g_wol);
    cudaGetSymbolAddress((void**)&Xh,  g_Xh);  cudaGetSymbolAddress((void**)&Xl,  g_Xl);
    cudaGetSymbolAddress((void**)&XIh, g_XIh); cudaGetSymbolAddress((void**)&XIl, g_XIl);
    cudaGetSymbolAddress((void**)&Hh,  g_Hh);  cudaGetSymbolAddress((void**)&Hl,  g_Hl);
    cudaGetSymbolAddress((void**)&Rh,  g_Rh);  cudaGetSymbolAddress((void**)&Rl,  g_Rl);
    cudaGetSymbolAddress((void**)&Ahb, g_Ahb); cudaGetSymbolAddress((void**)&Alb, g_Alb);

    cudaFuncSetAttribute(flash_attn, cudaFuncAttributeMaxDynamicSharedMemorySize, FLASH_SMEM);

    const dim3 tgrid512(CHALF / 128, NTOK / 128);   // (4, 32)
    const dim3 tgrid1024(CC / 128,  NTOK / 128);    // (8, 32)
    const int SPLIT_BLOCKS = NTOK * CC / 1024;      // 4096

    // weight prep (transpose + bf16 split)
    wsplit<<<dim3(CHALF / 32, CC / 32), 256>>>(imp_w1, wi1h, wi1l, CC, CHALF);
    wsplit<<<dim3(CC / 32, CC / 32), 256>>>(rsn_w1, wr1h, wr1l, CC, CC);
    wsplit<<<dim3(CC / 32, CC / 32), 256>>>(rsn_w2, wr2h, wr2l, CC, CC);
    wsplit<<<dim3(CC / 32, CC / 32), 256>>>(q_w,    wqh,  wql,  CC, CC);
    wsplit<<<dim3(CC / 32, CC / 32), 256>>>(k_w,    wkh,  wkl,  CC, CC);
    wsplit<<<dim3(CC / 32, CC / 32), 256>>>(v_w,    wvh,  wvl,  CC, CC);
    wsplit<<<dim3(CC / 32, CC / 32), 256>>>(o_w,    woh,  wol,  CC, CC);

    // importance net
    asplit<<<SPLIT_BLOCKS, 256>>>((const float4*)x, (uint2*)Xh, (uint2*)Xl);
    gemm_mma<<<tgrid512, 256>>>(Xh, Xl, wi1h, wi1l, imp_b1, H, CHALF);
    ln_rows<CHALF, true><<<NTOK, 256>>>(H, imp_g, imp_beta);
    importance_gate<<<NTOK, 256>>>(H, imp_w2, imp_b2, x, XI);

    // reasoning net
    asplit<<<SPLIT_BLOCKS, 256>>>((const float4*)XI, (uint2*)XIh, (uint2*)XIl);
    gemm_mma<<<tgrid1024, 256>>>(XIh, XIl, wr1h, wr1l, rsn_b1, H, CC);
    ln_rows<CC, true><<<NTOK, 256>>>(H, rsn_g, rsn_beta);
    asplit<<<SPLIT_BLOCKS, 256>>>((const float4*)H, (uint2*)Hh, (uint2*)Hl);
    gemm_mma<<<tgrid1024, 256>>>(Hh, Hl, wr2h, wr2l, rsn_b2, RSN, CC);

    // projections
    asplit<<<SPLIT_BLOCKS, 256>>>((const float4*)RSN, (uint2*)Rh, (uint2*)Rl);
    gemm_mma<<<tgrid1024, 256>>>(Rh,  Rl,  wqh, wql, q_b, Qb, CC);
    gemm_mma<<<tgrid1024, 256>>>(XIh, XIl, wkh, wkl, k_b, Kb, CC);
    gemm_mma<<<tgrid1024, 256>>>(Xh,  Xl,  wvh, wvl, v_b, Vb, CC);

    // temperature
    mean_rows<<<dim3(CC / 256, CB), 256>>>(RSN, MEANR);
    temp_net<<<CB, 512>>>(MEANR, tmp_w1, tmp_b1, tmp_g, tmp_beta,
                          tmp_w2, tmp_b2, TEMP);

    // attention
    flash_attn<<<dim3(CT / 64, CH, CB), 256, FLASH_SMEM>>>(Qb, Kb, Vb, mask,
                                                           TEMP, AO);

    // output projection + residual LN
    asplit<<<SPLIT_BLOCKS, 256>>>((const float4*)AO, (uint2*)Ahb, (uint2*)Alb);
    gemm_mma<<<tgrid1024, 256>>>(Ahb, Alb, woh, wol, o_b, PRJ, CC);
    residual_ln<<<NTOK, 256>>>(x, PRJ, norm_g, norm_b, out);
}